// round 13
// baseline (speedup 1.0000x reference)
#include <cuda_runtime.h>
#include <cuda_fp16.h>
#include <cstdint>
#include <math.h>

// POLY2: out_b = sigmoid( sum_{i<j} w_ij * x_bi * x_bj )
// tf32 mma.sync.m16n8k8 with ldmatrix.x4 fragment loads for BOTH operands.
// A = raw fp32 X (hardware tf32 truncation, no conversion anywhere);
// B = W pre-rounded rna->tf32 in prep. 3-stage cp.async, triangular K-skip,
// diagonal sub-block skip, heavy-tile-first, 2 CTAs/SM.

#define F        1024
#define BATCHN   16384
#define M_TILE   128
#define N_TILE   128
#define K_CHUNK  32
#define NTHREADS 256
#define NBLK     8
#define STAGES   3

#define ROW         144                      // smem row stride bytes (32 fp32 + 16B pad)
#define TILE_BYTES  (128 * ROW)              // 18432
#define STAGE_BYTES (2 * TILE_BYTES)         // 36864
#define PART_OFF    (STAGES * STAGE_BYTES)   // 110592
#define SMEM_TOTAL  (PART_OFF + 128 * 4)     // 111104

__device__ float d_Wt[F * F];             // Wt[n][k] = rna_tf32(w_{k,n}) (k<n else 0)
__device__ float d_part[NBLK * BATCHN];

// ---------------- helpers ----------------
__device__ __forceinline__ uint32_t smem_u32(const void* p) {
    uint32_t a;
    asm("{ .reg .u64 t; cvta.to.shared.u64 t, %1; cvt.u32.u64 %0, t; }" : "=r"(a) : "l"(p));
    return a;
}
__device__ __forceinline__ void cp16(uint32_t dst, const void* src) {
    asm volatile("cp.async.cg.shared.global [%0], [%1], 16;" :: "r"(dst), "l"(src) : "memory");
}
__device__ __forceinline__ void cp_commit() { asm volatile("cp.async.commit_group;" ::: "memory"); }
__device__ __forceinline__ void cp_wait1()  { asm volatile("cp.async.wait_group 1;"  ::: "memory"); }

__device__ __forceinline__ void ldsm4(uint32_t* r, uint32_t addr) {
    asm volatile("ldmatrix.sync.aligned.m8n8.x4.shared.b16 {%0,%1,%2,%3}, [%4];"
        : "=r"(r[0]), "=r"(r[1]), "=r"(r[2]), "=r"(r[3]) : "r"(addr));
}
// tf32 mma: C(f32x4) += A(tf32 x4) * B(tf32 x2)
__device__ __forceinline__ void mma_t(float* c, const uint32_t* a, uint32_t b0, uint32_t b1) {
    asm volatile(
        "mma.sync.aligned.m16n8k8.row.col.f32.tf32.tf32.f32 "
        "{%0,%1,%2,%3}, {%4,%5,%6,%7}, {%8,%9}, {%0,%1,%2,%3};"
        : "+f"(c[0]), "+f"(c[1]), "+f"(c[2]), "+f"(c[3])
        : "r"(a[0]), "r"(a[1]), "r"(a[2]), "r"(a[3]), "r"(b0), "r"(b1));
}

// ---------------- prep: W scatter (rna->tf32 bits, fp32 storage) ----------------
__device__ __forceinline__ float w_at(const float* __restrict__ w, int k, int n) {
    if (k >= n) return 0.0f;
    int pi = k * (F - 1) - (k * (k - 1)) / 2 + (n - k - 1);
    return w[pi];
}
__global__ void prep_w_kernel(const float* __restrict__ w) {
    int idx = (blockIdx.x * 256 + threadIdx.x) * 2;   // over F*F, 2 elts/thread
    int n  = idx >> 10;
    int k  = idx & (F - 1);
    uint32_t v0, v1;
    asm("cvt.rna.tf32.f32 %0, %1;" : "=r"(v0) : "f"(w_at(w, k, n)));
    asm("cvt.rna.tf32.f32 %0, %1;" : "=r"(v1) : "f"(w_at(w, k + 1, n)));
    float2 o;
    o.x = __uint_as_float(v0);
    o.y = __uint_as_float(v1);
    *reinterpret_cast<float2*>(d_Wt + idx) = o;
}

__global__ void sigmoid_kernel(float* __restrict__ out) {
    int i = blockIdx.x * 256 + threadIdx.x;
    float z = 0.0f;
    #pragma unroll
    for (int j = 0; j < NBLK; ++j) z += d_part[j * BATCHN + i];
    out[i] = 1.0f / (1.0f + __expf(-z));
}

// ---------------- chunk compute body ----------------
// TAIL: diagonal-region chunk (d = 32*ck - n0 in {0,32,64,96}); skip mma
// sub-blocks with k_lo >= n_hi (strictly-upper-tri W).
template<bool TAIL>
__device__ __forceinline__ void chunk_body(uint32_t aAddr, uint32_t bAddr,
                                           float acc[2][8][4],
                                           int d, int warpN) {
    #pragma unroll
    for (int ks = 0; ks < 4; ++ks) {
        uint32_t a[2][4];
        ldsm4(a[0], aAddr + ks * 32);
        ldsm4(a[1], aAddr + 16 * ROW + ks * 32);
        #pragma unroll
        for (int g = 0; g < 4; ++g) {
            if (TAIL) {
                // nt=2g+1 block zero => nt=2g zero too => skip ldsm + both
                if (!((d + 8 * ks) < (warpN * 64 + (2 * g + 1) * 8 + 8))) continue;
            }
            uint32_t b[4];      // r0=b0(2g) r1=b1(2g) r2=b0(2g+1) r3=b1(2g+1)
            ldsm4(b, bAddr + (uint32_t)(g * 16) * ROW + ks * 32);
            bool nz0 = !TAIL || ((d + 8 * ks) < (warpN * 64 + 2 * g * 8 + 8));
            if (nz0) {
                mma_t(acc[0][2 * g], a[0], b[0], b[1]);
                mma_t(acc[1][2 * g], a[1], b[0], b[1]);
            }
            mma_t(acc[0][2 * g + 1], a[0], b[2], b[3]);
            mma_t(acc[1][2 * g + 1], a[1], b[2], b[3]);
        }
    }
}

// ---------------- main GEMM + fused rowdot ----------------
extern __shared__ char smem_buf[];

__global__ void __launch_bounds__(NTHREADS, 2)
poly2_gemm_kernel(const float* __restrict__ x) {
    uint32_t sb = smem_u32(smem_buf);
    float* part = reinterpret_cast<float*>(smem_buf + PART_OFF);

    int tid  = threadIdx.x;
    int lane = tid & 31;
    int wid  = tid >> 5;
    int warpM = wid & 3;                 // 4 warps along M (tile 32)
    int warpN = wid >> 2;                // 2 warps along N (tile 64)
    int m0 = blockIdx.x * M_TILE;
    int by = (int)gridDim.y - 1 - (int)blockIdx.y;   // heavy tiles first
    int n0 = by * N_TILE;

    int nchunks = (n0 + N_TILE) / K_CHUNK;           // 4..32 (triangular skip)

    // loader: 128 rows x 8 16B-chunks per tile, fp32 (32 floats/row)
    int lrow = tid >> 3, lcol = tid & 7;
    const float* agp = x    + (size_t)(m0 + lrow) * F + lcol * 4;
    const float* bgp = d_Wt + (size_t)(n0 + lrow) * F + lcol * 4;
    uint32_t sdoff = (uint32_t)(lrow * ROW + lcol * 16);

    #define ISSUE_STAGE(sidx)                                            \
        do {                                                             \
            uint32_t ab = sb + (uint32_t)(sidx) * STAGE_BYTES + sdoff;   \
            _Pragma("unroll")                                            \
            for (int j = 0; j < 4; ++j)                                  \
                cp16(ab + j * (32 * ROW), agp + j * (32 * F));           \
            uint32_t bb = ab + TILE_BYTES;                               \
            _Pragma("unroll")                                            \
            for (int j = 0; j < 4; ++j)                                  \
                cp16(bb + j * (32 * ROW), bgp + j * (32 * F));           \
            agp += K_CHUNK; bgp += K_CHUNK;                              \
        } while (0)

    float acc[2][8][4];
    #pragma unroll
    for (int mt = 0; mt < 2; ++mt)
        #pragma unroll
        for (int nt = 0; nt < 8; ++nt)
            #pragma unroll
            for (int r = 0; r < 4; ++r) acc[mt][nt][r] = 0.0f;

    ISSUE_STAGE(0); cp_commit();
    ISSUE_STAGE(1); cp_commit();
    cp_wait1();
    __syncthreads();

    // per-lane ldmatrix offsets (b32 8x8 via paired b16 matrices)
    // A: q=l>>3: row += (q&1)*8, byte += (q>>1)*16
    uint32_t aoff = ((uint32_t)(((lane >> 3) & 1) * 8 + (lane & 7))) * ROW
                  + (uint32_t)((lane >> 4) & 1) * 16
                  + (uint32_t)(warpM * 32) * ROW;
    // B: q=l>>3: row += (q>>1)*8, byte += (q&1)*16
    uint32_t boff = ((uint32_t)(((lane >> 4) & 1) * 8 + (lane & 7))) * ROW
                  + (uint32_t)((lane >> 3) & 1) * 16
                  + (uint32_t)(warpN * 64) * ROW + TILE_BYTES;

    int sidx = 2;
    for (int ck = 0; ck < nchunks; ++ck) {
        if (ck + 2 < nchunks) {
            ISSUE_STAGE(sidx);
        }
        cp_commit();
        if (++sidx == STAGES) sidx = 0;

        uint32_t stbase = sb + (uint32_t)(ck % STAGES) * STAGE_BYTES;
        if (ck < nchunks - 4)
            chunk_body<false>(stbase + aoff, stbase + boff, acc, 0, warpN);
        else
            chunk_body<true>(stbase + aoff, stbase + boff, acc,
                             32 * ck - n0, warpN);   // d in {0,32,64,96}

        cp_wait1();
        __syncthreads();
    }

    // ---------------- epilogue: rowdot S * x (fp32 direct) ----------------
    if (tid < 128) part[tid] = 0.0f;
    __syncthreads();

    #pragma unroll
    for (int mt = 0; mt < 2; ++mt) {
        float ps0 = 0.0f, ps1 = 0.0f;
        #pragma unroll
        for (int nt = 0; nt < 8; ++nt) {
            int col  = n0 + warpN * 64 + nt * 8 + (lane & 3) * 2;
            int rowg = m0 + warpM * 32 + mt * 16 + (lane >> 2);
            float2 x0 = *reinterpret_cast<const float2*>(x + (size_t)rowg * F + col);
            float2 x1 = *reinterpret_cast<const float2*>(x + (size_t)(rowg + 8) * F + col);
            ps0 += acc[mt][nt][0] * x0.x + acc[mt][nt][1] * x0.y;
            ps1 += acc[mt][nt][2] * x1.x + acc[mt][nt][3] * x1.y;
        }
        ps0 += __shfl_xor_sync(0xffffffffu, ps0, 1);
        ps0 += __shfl_xor_sync(0xffffffffu, ps0, 2);
        ps1 += __shfl_xor_sync(0xffffffffu, ps1, 1);
        ps1 += __shfl_xor_sync(0xffffffffu, ps1, 2);
        if ((lane & 3) == 0) {
            int rl = warpM * 32 + mt * 16 + (lane >> 2);
            atomicAdd(&part[rl], ps0);
            atomicAdd(&part[rl + 8], ps1);
        }
    }
    __syncthreads();
    if (tid < 128) d_part[by * BATCHN + m0 + tid] = part[tid];
}

// ---------------- launch ----------------
extern "C" void kernel_launch(void* const* d_in, const int* in_sizes, int n_in,
                              void* d_out, int out_size) {
    const float* x = (const float*)d_in[0];
    const float* w = (const float*)d_in[1];
    float* out = (float*)d_out;

    prep_w_kernel<<<(F * F / 2) / 256, 256>>>(w);

    cudaFuncSetAttribute(poly2_gemm_kernel,
                         cudaFuncAttributeMaxDynamicSharedMemorySize, SMEM_TOTAL);
    dim3 grid(BATCHN / M_TILE, NBLK);
    poly2_gemm_kernel<<<grid, NTHREADS, SMEM_TOTAL>>>(x);

    sigmoid_kernel<<<BATCHN / 256, 256>>>(out);
}